// round 4
// baseline (speedup 1.0000x reference)
#include <cuda_runtime.h>
#include <cuda_bf16.h>
#include <cstdint>

#define N_NODES 50000
#define N_EDGES 800000
#define DIM     128

#define SCAN_NBLK ((N_NODES + 255) / 256)   // 196

// -------- device scratch (no allocations allowed) --------
__device__ float g_agg[(size_t)N_NODES * DIM];   // normalized neighbor mean
__device__ float g_h0 [(size_t)N_NODES * DIM];
__device__ float g_h1 [(size_t)N_NODES * DIM];
__device__ float g_invdeg[N_NODES];
__device__ int   g_cnt[N_NODES];
__device__ int   g_cursor[N_NODES];
__device__ int   g_rowptr[N_NODES + 1];
__device__ int   g_blocksum[SCAN_NBLK];
__device__ int   g_csr_src[N_EDGES];

// ============ CSR build (once per launch) ============
__global__ void k_zero_cnt() {
    int i = blockIdx.x * blockDim.x + threadIdx.x;
    if (i < N_NODES) { g_cnt[i] = 0; g_cursor[i] = 0; }
}
__global__ void k_count(const int* __restrict__ dst) {
    int e = blockIdx.x * blockDim.x + threadIdx.x;
    if (e < N_EDGES) atomicAdd(&g_cnt[dst[e]], 1);
}
// per-block sums of 256-element chunks
__global__ void k_scan1() {
    __shared__ int s[256];
    int i = blockIdx.x * 256 + threadIdx.x;
    int v = (i < N_NODES) ? g_cnt[i] : 0;
    s[threadIdx.x] = v;
    __syncthreads();
    for (int off = 128; off > 0; off >>= 1) {
        if (threadIdx.x < off) s[threadIdx.x] += s[threadIdx.x + off];
        __syncthreads();
    }
    if (threadIdx.x == 0) g_blocksum[blockIdx.x] = s[0];
}
// exclusive scan of block sums (single block)
__global__ void k_scan2() {
    __shared__ int s[256];
    int t = threadIdx.x;
    int v = (t < SCAN_NBLK) ? g_blocksum[t] : 0;
    s[t] = v;
    __syncthreads();
    for (int off = 1; off < 256; off <<= 1) {
        int x = (t >= off) ? s[t - off] : 0;
        __syncthreads();
        s[t] += x;
        __syncthreads();
    }
    if (t < SCAN_NBLK) g_blocksum[t] = s[t] - v;   // exclusive
}
// per-chunk exclusive scan + offset -> rowptr; also invdeg
__global__ void k_scan3() {
    __shared__ int s[256];
    int t = threadIdx.x;
    int i = blockIdx.x * 256 + t;
    int v = (i < N_NODES) ? g_cnt[i] : 0;
    s[t] = v;
    __syncthreads();
    for (int off = 1; off < 256; off <<= 1) {
        int x = (t >= off) ? s[t - off] : 0;
        __syncthreads();
        s[t] += x;
        __syncthreads();
    }
    if (i < N_NODES) {
        g_rowptr[i] = g_blocksum[blockIdx.x] + s[t] - v;   // exclusive
        g_invdeg[i] = 1.0f / fmaxf((float)v, 1.0f);
    }
    if (i == 0) g_rowptr[N_NODES] = N_EDGES;
}
__global__ void k_fill(const int* __restrict__ src, const int* __restrict__ dst) {
    int e = blockIdx.x * blockDim.x + threadIdx.x;
    if (e < N_EDGES) {
        int d = dst[e];
        int pos = g_rowptr[d] + atomicAdd(&g_cursor[d], 1);
        g_csr_src[pos] = src[e];
    }
}

// ============ gather aggregation: one warp per dst node ============
// g_agg[v] = invdeg[v] * sum_{u in N(v)} h[u]
__global__ void k_gather(const float* __restrict__ h) {
    int warp = (blockIdx.x * blockDim.x + threadIdx.x) >> 5;
    int lane = threadIdx.x & 31;
    if (warp >= N_NODES) return;
    int beg = g_rowptr[warp];
    int end = g_rowptr[warp + 1];
    float4 acc = make_float4(0.f, 0.f, 0.f, 0.f);
    for (int i = beg; i < end; i++) {
        int s = g_csr_src[i];
        float4 v = __ldg((const float4*)(h + (size_t)s * DIM) + lane);
        acc.x += v.x; acc.y += v.y; acc.z += v.z; acc.w += v.w;
    }
    float idg = g_invdeg[warp];
    acc.x *= idg; acc.y *= idg; acc.z *= idg; acc.w *= idg;
    ((float4*)(g_agg + (size_t)warp * DIM))[lane] = acc;
}

// ============ GEMM: out = [h | g_agg](M x 256) @ [Wself; Wneigh](256x128) + b ============
template <bool RELU>
__global__ __launch_bounds__(256) void k_gemm(const float* __restrict__ h,
                                              const float* __restrict__ Wself,
                                              const float* __restrict__ Wneigh,
                                              const float* __restrict__ bias,
                                              float* __restrict__ out) {
    constexpr int BM = 128, BN = 128, BK = 16, TM = 8, TN = 8;
    __shared__ float As[BK][BM];
    __shared__ float Bs[BK][BN];

    const int tid = threadIdx.x;           // 256 threads
    const int row0 = blockIdx.x * BM;
    const int tx = tid & 15;               // 16 col groups of TN=8
    const int ty = tid >> 4;               // 16 row groups of TM=8

    float acc[TM][TN];
#pragma unroll
    for (int i = 0; i < TM; i++)
#pragma unroll
        for (int j = 0; j < TN; j++) acc[i][j] = 0.f;

    // A-tile: 128 rows x 16 k; each thread 2 float4 along K of one row
    const int arow = tid >> 1;             // 0..127
    const int ak   = (tid & 1) * 8;        // 0 or 8
    const int grow = row0 + arow;
    const bool rowok = (grow < N_NODES);

    // B-tile: 16 k-rows x 128 cols; each thread 8 consecutive floats
    const int brow = tid >> 4;             // 0..15
    const int bcol = (tid & 15) * 8;       // 0..120

    for (int k0 = 0; k0 < 2 * DIM; k0 += BK) {
        // ---- A: virtual [h | g_agg] ----
        {
            int kk = k0 + ak;
            const float* Ap = (kk < DIM) ? (h + (size_t)grow * DIM + kk)
                                         : (g_agg + (size_t)grow * DIM + (kk - DIM));
            float4 a0 = make_float4(0.f,0.f,0.f,0.f), a1 = a0;
            if (rowok) {
                a0 = *(const float4*)Ap;
                a1 = *(const float4*)(Ap + 4);
            }
            As[ak + 0][arow] = a0.x; As[ak + 1][arow] = a0.y;
            As[ak + 2][arow] = a0.z; As[ak + 3][arow] = a0.w;
            As[ak + 4][arow] = a1.x; As[ak + 5][arow] = a1.y;
            As[ak + 6][arow] = a1.z; As[ak + 7][arow] = a1.w;
        }
        // ---- B: stacked [Wself; Wneigh] ----
        {
            int kk = k0 + brow;
            const float* Wp = (kk < DIM) ? (Wself + (size_t)kk * DIM)
                                         : (Wneigh + (size_t)(kk - DIM) * DIM);
            *(float4*)&Bs[brow][bcol]     = *(const float4*)(Wp + bcol);
            *(float4*)&Bs[brow][bcol + 4] = *(const float4*)(Wp + bcol + 4);
        }
        __syncthreads();

#pragma unroll
        for (int k = 0; k < BK; k++) {
            float a[TM], w[TN];
            *(float4*)&a[0] = *(const float4*)&As[k][ty * TM];
            *(float4*)&a[4] = *(const float4*)&As[k][ty * TM + 4];
            *(float4*)&w[0] = *(const float4*)&Bs[k][tx * TN];
            *(float4*)&w[4] = *(const float4*)&Bs[k][tx * TN + 4];
#pragma unroll
            for (int i = 0; i < TM; i++)
#pragma unroll
                for (int j = 0; j < TN; j++) acc[i][j] += a[i] * w[j];
        }
        __syncthreads();
    }

    // ---- epilogue: bias (+relu) ----
    const int c = tx * TN;
    float4 b0 = *(const float4*)(bias + c);
    float4 b1 = *(const float4*)(bias + c + 4);
#pragma unroll
    for (int i = 0; i < TM; i++) {
        int r = row0 + ty * TM + i;
        if (r < N_NODES) {
            float v[TN];
            v[0] = acc[i][0] + b0.x; v[1] = acc[i][1] + b0.y;
            v[2] = acc[i][2] + b0.z; v[3] = acc[i][3] + b0.w;
            v[4] = acc[i][4] + b1.x; v[5] = acc[i][5] + b1.y;
            v[6] = acc[i][6] + b1.z; v[7] = acc[i][7] + b1.w;
            if (RELU) {
#pragma unroll
                for (int j = 0; j < TN; j++) v[j] = fmaxf(v[j], 0.f);
            }
            *(float4*)(out + (size_t)r * DIM + c)     = *(float4*)&v[0];
            *(float4*)(out + (size_t)r * DIM + c + 4) = *(float4*)&v[4];
        }
    }
}

extern "C" void kernel_launch(void* const* d_in, const int* in_sizes, int n_in,
                              void* d_out, int out_size) {
    const float* x      = (const float*)d_in[0];
    const int*   src    = (const int*)d_in[1];
    const int*   dst    = (const int*)d_in[2];
    const float* W_self = (const float*)d_in[3];   // [3,128,128]
    const float* W_neigh= (const float*)d_in[4];   // [3,128,128]
    const float* b      = (const float*)d_in[5];   // [3,128]
    float* out = (float*)d_out;

    const int TPB = 256;
    const int nblk_nodes = (N_NODES + TPB - 1) / TPB;
    const int nblk_edges = (N_EDGES + TPB - 1) / TPB;
    const int nblk_gath  = (N_NODES * 32 + TPB - 1) / TPB;  // warp per node
    const int nblk_gemm  = (N_NODES + 127) / 128;

    // ---- CSR build (once; graph shared across layers) ----
    k_zero_cnt<<<nblk_nodes, TPB>>>();
    k_count<<<nblk_edges, TPB>>>(dst);
    k_scan1<<<SCAN_NBLK, 256>>>();
    k_scan2<<<1, 256>>>();
    k_scan3<<<SCAN_NBLK, 256>>>();
    k_fill<<<nblk_edges, TPB>>>(src, dst);

    const size_t WSZ = (size_t)DIM * DIM;

    // layer 0: x -> g_h0 (relu)
    k_gather<<<nblk_gath, TPB>>>(x);
    k_gemm<true><<<nblk_gemm, TPB>>>(x, W_self + 0 * WSZ, W_neigh + 0 * WSZ,
                                     b + 0 * DIM, g_h0);
    // layer 1: g_h0 -> g_h1 (relu)
    k_gather<<<nblk_gath, TPB>>>(g_h0);
    k_gemm<true><<<nblk_gemm, TPB>>>(g_h0, W_self + 1 * WSZ, W_neigh + 1 * WSZ,
                                     b + 1 * DIM, g_h1);
    // layer 2: g_h1 -> out (no relu)
    k_gather<<<nblk_gath, TPB>>>(g_h1);
    k_gemm<false><<<nblk_gemm, TPB>>>(g_h1, W_self + 2 * WSZ, W_neigh + 2 * WSZ,
                                      b + 2 * DIM, out);
}